// round 11
// baseline (speedup 1.0000x reference)
#include <cuda_runtime.h>
#include <cstdint>

#define TPB    192        // one thread per 8 floats of a 1536-float row
#define BAND   16         // output rows per block
#define NROWS  (BAND + 4) // input rows consumed per band
#define HH     384
#define ROWF   1536
#define NBANDS (HH / BAND)
#define DEPTH  4          // smem ring slots per warp
#define SLOTF  272        // floats/slot: 8 hdr (6 L-halo) + 256 chunk + 6 R-halo + pad

static __device__ __forceinline__ int hrefl(int h) {
    h = (h < 0) ? -h : h;
    return (h >= HH) ? (2 * HH - 2 - h) : h;
}

// Gaussian taps for ksize=5, sigma=1.1 (OpenCV default), normalized.
#define C0 0.07076630f
#define C1 0.24446028f
#define C2 0.36954642f

struct F8 { float v[8]; };

static __device__ __forceinline__ uint32_t s2u(const void* p) {
    uint32_t a;
    asm("{ .reg .u64 t; cvta.to.shared.u64 t, %1; cvt.u32.u64 %0, t; }"
        : "=r"(a) : "l"(p));
    return a;
}
static __device__ __forceinline__ void cp16(uint32_t dst, const void* src) {
    asm volatile("cp.async.ca.shared.global [%0], [%1], 16;" :: "r"(dst), "l"(src));
}
static __device__ __forceinline__ void cp8(uint32_t dst, const void* src) {
    asm volatile("cp.async.ca.shared.global [%0], [%1], 8;" :: "r"(dst), "l"(src));
}
static __device__ __forceinline__ void cp_commit() {
    asm volatile("cp.async.commit_group;" ::: "memory");
}
// Wait until at most 3 groups are pending: with one commit per row, the row
// 3 commits back (and older) is guaranteed complete.
static __device__ __forceinline__ void cp_wait3() {
    asm volatile("cp.async.wait_group 3;" ::: "memory");
}

// Stage one input row's worth for this thread into slot: 32B chunk + (edge
// lanes) the cross-warp halo into the slot header/footer. Pure async copies.
static __device__ __forceinline__ void issue_row(
    const float* __restrict__ rw,   // row base + 256*warp (warp's first flat)
    float* slot, int lane, int t)
{
    uint32_t sb = s2u(slot);
    const float* src = rw + 8 * lane;
    uint32_t dst = sb + 32 + 32 * lane;         // chunk floats [8 + 8*lane ...]
    cp16(dst,      src);
    cp16(dst + 16, src + 4);
    if (lane == 0 && t > 0) {                   // L halo: flats -6..-1 -> slot[2..7]
        cp8(sb + 8,  rw - 6);
        cp8(sb + 16, rw - 4);
        cp8(sb + 24, rw - 2);
    }
    if (lane == 31 && t < TPB - 1) {            // R halo: flats 256..261 -> slot[264..269]
        cp16(sb + 32 + 1024, rw + 256);
        cp8 (sb + 32 + 1040, rw + 260);
    }
}

// Horizontal blur of this thread's 8 floats from the staged slot. Uniform
// unaligned-LDS addressing (edge lanes read the staged halo); image width
// edges fold reflect-101 into a register permutation.
static __device__ __forceinline__ F8 hb_slot(const float* __restrict__ slot, int lane, int t)
{
    const float* p = slot + 8 + 8 * lane;
    float2 La = *(const float2*)(p - 6);
    float4 Lb = *(const float4*)(p - 4);
    float4 Cb = *(const float4*)(p);
    float4 Db = *(const float4*)(p + 4);
    float4 Rb = *(const float4*)(p + 8);
    float2 Ra = *(const float2*)(p + 12);

    float e0 = La.x, e1 = La.y, e2 = Lb.x, e3 = Lb.y, e4 = Lb.z, e5 = Lb.w;
    float e14 = Rb.x, e15 = Rb.y, e16 = Rb.z, e17 = Rb.w, e18 = Ra.x, e19 = Ra.y;

    if (t == 0) {            // flats -6..-1 -> reflected {6,7,8,3,4,5}
        e0 = Db.z; e1 = Db.w; e2 = e14; e3 = Cb.w; e4 = Db.x; e5 = Db.y;
    }
    if (t == TPB - 1) {      // flats 1536..1541 -> {1530,1531,1532,1527,1528,1529}
        e14 = Cb.z; e15 = Cb.w; e16 = Db.x; e17 = e5; e18 = Cb.x; e19 = Cb.y;
    }

    const float e6 = Cb.x, e7 = Cb.y, e8 = Cb.z, e9 = Cb.w;
    const float e10 = Db.x, e11 = Db.y, e12 = Db.z, e13 = Db.w;

    F8 o;
    o.v[0] = C0 * (e0 + e12) + C1 * (e3  + e9)  + C2 * e6;
    o.v[1] = C0 * (e1 + e13) + C1 * (e4  + e10) + C2 * e7;
    o.v[2] = C0 * (e2 + e14) + C1 * (e5  + e11) + C2 * e8;
    o.v[3] = C0 * (e3 + e15) + C1 * (e6  + e12) + C2 * e9;
    o.v[4] = C0 * (e4 + e16) + C1 * (e7  + e13) + C2 * e10;
    o.v[5] = C0 * (e5 + e17) + C1 * (e8  + e14) + C2 * e11;
    o.v[6] = C0 * (e6 + e18) + C1 * (e9  + e15) + C2 * e12;
    o.v[7] = C0 * (e7 + e19) + C1 * (e10 + e16) + C2 * e13;
    return o;
}

__global__ void __launch_bounds__(TPB, 4)
gauss5_kernel(const float* __restrict__ x, float* __restrict__ y)
{
    __shared__ __align__(16) float ring[TPB / 32][DEPTH][SLOTF];   // 25.5 KB

    const int t    = threadIdx.x;
    const int lane = t & 31;
    const int wp   = t >> 5;
    const int h0   = blockIdx.x * BAND;
    const long img = blockIdx.y;

    const float* __restrict__ ib = x + img * (long)(HH * ROWF);
    float*       __restrict__ ob = y + img * (long)(HH * ROWF) + 8 * t;
    const int wbase = 256 * wp;   // warp's first flat within a row

    // Prologue: stage input rows k = 0..3 (row h0-2+k) into slots 0..3.
    #pragma unroll
    for (int k = 0; k < DEPTH; k++) {
        issue_row(ib + (long)hrefl(h0 - 2 + k) * ROWF + wbase,
                  &ring[wp][k][0], lane, t);
        cp_commit();
    }

    // Rows k = 0..3 fill the vertical window (no output). Consuming row k:
    // committed groups = rows 0..k+3, wait_group 3 -> row k complete.
    F8 w0, w1, w2, w3;
    #pragma unroll
    for (int k = 0; k < 4; k++) {
        cp_wait3();
        __syncwarp();
        F8 w = hb_slot(&ring[wp][k & 3][0], lane, t);
        if (k == 0) w0 = w; else if (k == 1) w1 = w;
        else if (k == 2) w2 = w; else w3 = w;
        __syncwarp();                       // reads done before slot reuse
        issue_row(ib + (long)hrefl(h0 - 2 + k + DEPTH) * ROWF + wbase,
                  &ring[wp][k & 3][0], lane, t);
        cp_commit();
    }

    // Main: consuming input row k emits output row h0 + k - 4.
    #pragma unroll 4
    for (int k = 4; k < NROWS; k++) {
        cp_wait3();
        __syncwarp();
        F8 w4 = hb_slot(&ring[wp][k & 3][0], lane, t);
        __syncwarp();                       // reads done before slot reuse
        if (k + DEPTH < NROWS) {
            issue_row(ib + (long)hrefl(h0 - 2 + k + DEPTH) * ROWF + wbase,
                      &ring[wp][k & 3][0], lane, t);
        }
        cp_commit();                        // 1:1 group-per-row accounting

        float4 oa, obv;
        oa.x  = C0 * (w0.v[0] + w4.v[0]) + C1 * (w1.v[0] + w3.v[0]) + C2 * w2.v[0];
        oa.y  = C0 * (w0.v[1] + w4.v[1]) + C1 * (w1.v[1] + w3.v[1]) + C2 * w2.v[1];
        oa.z  = C0 * (w0.v[2] + w4.v[2]) + C1 * (w1.v[2] + w3.v[2]) + C2 * w2.v[2];
        oa.w  = C0 * (w0.v[3] + w4.v[3]) + C1 * (w1.v[3] + w3.v[3]) + C2 * w2.v[3];
        obv.x = C0 * (w0.v[4] + w4.v[4]) + C1 * (w1.v[4] + w3.v[4]) + C2 * w2.v[4];
        obv.y = C0 * (w0.v[5] + w4.v[5]) + C1 * (w1.v[5] + w3.v[5]) + C2 * w2.v[5];
        obv.z = C0 * (w0.v[6] + w4.v[6]) + C1 * (w1.v[6] + w3.v[6]) + C2 * w2.v[6];
        obv.w = C0 * (w0.v[7] + w4.v[7]) + C1 * (w1.v[7] + w3.v[7]) + C2 * w2.v[7];

        float* op = ob + (long)(h0 + k - 4) * ROWF;
        *(float4*)op       = oa;
        *(float4*)(op + 4) = obv;

        w0 = w1; w1 = w2; w2 = w3; w3 = w4;
    }
}

extern "C" void kernel_launch(void* const* d_in, const int* in_sizes, int n_in,
                              void* d_out, int out_size)
{
    const float* x = (const float*)d_in[0];
    float* y = (float*)d_out;
    const int batch = in_sizes[0] / (HH * ROWF);   // 64
    dim3 grid(NBANDS, batch);
    gauss5_kernel<<<grid, TPB>>>(x, y);
}

// round 12
// speedup vs baseline: 1.0720x; 1.0720x over previous
#include <cuda_runtime.h>
#include <cuda_fp16.h>

#define TPB    192        // one thread per 8 floats of a 1536-float row
#define NCOLS  192
#define BAND   16         // output rows per block
#define HH     384
#define ROWF   1536       // W*C floats per row
#define NBANDS (HH / BAND)

static __device__ __forceinline__ int hrefl(int h) {
    // reflect-101 along height; used only for h in [-2, HH+1]
    h = (h < 0) ? -h : h;
    return (h >= HH) ? (2 * HH - 2 - h) : h;
}

// Gaussian taps for ksize=5, sigma=1.1 (OpenCV default), normalized.
#define C0 0.07076630f    /* w[0] = w[4] */
#define C1 0.24446028f    /* w[1] = w[3] */
#define C2 0.36954642f    /* w[2]        */

struct F8 { float v[8]; };
struct H8 { __half2 h[4]; };   // fp16-compressed hb row (8 values, 16 bytes)

static __device__ __forceinline__ H8 packF8(const F8& f) {
    H8 o;
    #pragma unroll
    for (int j = 0; j < 4; j++)
        o.h[j] = __floats2half2_rn(f.v[2 * j], f.v[2 * j + 1]);
    return o;
}

// Load row h and horizontally blur this thread's 8 floats (flats 8g..8g+7).
// Intra-warp halo via shuffles; warp-edge lanes load their 6-float halo;
// image width edges fold reflect-101 into a register permutation.
// (Identical to the 63.6us R4 kernel.)
static __device__ __forceinline__ F8 hb_row(
    const float* __restrict__ ib, int h, int g, int lane)
{
    const float* __restrict__ rp = ib + (long)hrefl(h) * ROWF + 8 * g;
    float4 Cb = *(const float4*)(rp);       // flats 8g   .. 8g+3
    float4 Db = *(const float4*)(rp + 4);   // flats 8g+4 .. 8g+7

    // e[k] = flat(8g - 6 + k), k = 0..19
    float e0  = __shfl_up_sync(0xffffffffu, Cb.z, 1);
    float e1  = __shfl_up_sync(0xffffffffu, Cb.w, 1);
    float e2  = __shfl_up_sync(0xffffffffu, Db.x, 1);
    float e3  = __shfl_up_sync(0xffffffffu, Db.y, 1);
    float e4  = __shfl_up_sync(0xffffffffu, Db.z, 1);
    float e5  = __shfl_up_sync(0xffffffffu, Db.w, 1);
    float e14 = __shfl_down_sync(0xffffffffu, Cb.x, 1);
    float e15 = __shfl_down_sync(0xffffffffu, Cb.y, 1);
    float e16 = __shfl_down_sync(0xffffffffu, Cb.z, 1);
    float e17 = __shfl_down_sync(0xffffffffu, Cb.w, 1);
    float e18 = __shfl_down_sync(0xffffffffu, Db.x, 1);
    float e19 = __shfl_down_sync(0xffffffffu, Db.y, 1);

    if (lane == 0 && g > 0) {
        float2 a = *(const float2*)(rp - 6);
        float4 b = *(const float4*)(rp - 4);
        e0 = a.x; e1 = a.y; e2 = b.x; e3 = b.y; e4 = b.z; e5 = b.w;
    }
    if (lane == 31 && g < NCOLS - 1) {
        float4 b = *(const float4*)(rp + 8);
        float2 a = *(const float2*)(rp + 12);
        e14 = b.x; e15 = b.y; e16 = b.z; e17 = b.w; e18 = a.x; e19 = a.y;
    }
    if (g == 0) {            // flats -6..-1 -> reflected {6,7,8,3,4,5}
        e0 = Db.z; e1 = Db.w; e2 = e14; e3 = Cb.w; e4 = Db.x; e5 = Db.y;
    }
    if (g == NCOLS - 1) {    // flats 1536..1541 -> {1530,1531,1532,1527,1528,1529}
        e14 = Cb.z; e15 = Cb.w; e16 = Db.x; e17 = e5; e18 = Cb.x; e19 = Cb.y;
    }

    const float e6 = Cb.x, e7 = Cb.y, e8 = Cb.z, e9 = Cb.w;
    const float e10 = Db.x, e11 = Db.y, e12 = Db.z, e13 = Db.w;

    // Horizontal taps at flat offsets {-6,-3,0,+3,+6}.
    F8 o;
    o.v[0] = C0 * (e0 + e12) + C1 * (e3  + e9)  + C2 * e6;
    o.v[1] = C0 * (e1 + e13) + C1 * (e4  + e10) + C2 * e7;
    o.v[2] = C0 * (e2 + e14) + C1 * (e5  + e11) + C2 * e8;
    o.v[3] = C0 * (e3 + e15) + C1 * (e6  + e12) + C2 * e9;
    o.v[4] = C0 * (e4 + e16) + C1 * (e7  + e13) + C2 * e10;
    o.v[5] = C0 * (e5 + e17) + C1 * (e8  + e14) + C2 * e11;
    o.v[6] = C0 * (e6 + e18) + C1 * (e9  + e15) + C2 * e12;
    o.v[7] = C0 * (e7 + e19) + C1 * (e10 + e16) + C2 * e13;
    return o;
}

__global__ void __launch_bounds__(TPB, 5)
gauss5_kernel(const float* __restrict__ x, float* __restrict__ y)
{
    const int t    = threadIdx.x;
    const int lane = t & 31;
    const int h0   = blockIdx.x * BAND;
    const long img = blockIdx.y;

    const float* __restrict__ ib = x + img * (long)(HH * ROWF);
    float*       __restrict__ ob = y + img * (long)(HH * ROWF) + 8 * t;

    // 4-row sliding window of horizontally-blurred values, fp16-compressed.
    H8 w0 = packF8(hb_row(ib, h0 - 2, t, lane));
    H8 w1 = packF8(hb_row(ib, h0 - 1, t, lane));
    H8 w2 = packF8(hb_row(ib, h0,     t, lane));
    H8 w3 = packF8(hb_row(ib, h0 + 1, t, lane));

    #pragma unroll 4
    for (int r = 0; r < BAND; r++) {
        F8 w4 = hb_row(ib, h0 + r + 2, t, lane);

        // Vertical pass: unpack window to fp32, combine in fp32.
        float o[8];
        #pragma unroll
        for (int j = 0; j < 4; j++) {
            float2 f0 = __half22float2(w0.h[j]);
            float2 f1 = __half22float2(w1.h[j]);
            float2 f2 = __half22float2(w2.h[j]);
            float2 f3 = __half22float2(w3.h[j]);
            o[2 * j]     = C0 * (f0.x + w4.v[2 * j])     + C1 * (f1.x + f3.x) + C2 * f2.x;
            o[2 * j + 1] = C0 * (f0.y + w4.v[2 * j + 1]) + C1 * (f1.y + f3.y) + C2 * f2.y;
        }

        float* op = ob + (long)(h0 + r) * ROWF;
        *(float4*)op       = make_float4(o[0], o[1], o[2], o[3]);
        *(float4*)(op + 4) = make_float4(o[4], o[5], o[6], o[7]);

        w0 = w1; w1 = w2; w2 = w3; w3 = packF8(w4);
    }
}

extern "C" void kernel_launch(void* const* d_in, const int* in_sizes, int n_in,
                              void* d_out, int out_size)
{
    const float* x = (const float*)d_in[0];
    float* y = (float*)d_out;
    const int batch = in_sizes[0] / (HH * ROWF);   // 64
    dim3 grid(NBANDS, batch);
    gauss5_kernel<<<grid, TPB>>>(x, y);
}

// round 13
// speedup vs baseline: 1.1230x; 1.0475x over previous
#include <cuda_runtime.h>
#include <cuda_fp16.h>

#define TPB    192        // one thread per 8 floats of a 1536-float row
#define NCOLS  192
#define BAND   16         // output rows per block
#define HH     384
#define ROWF   1536       // W*C floats per row
#define NBANDS (HH / BAND)

static __device__ __forceinline__ int hrefl(int h) {
    // reflect-101 along height; used only for h in [-2, HH+1]
    h = (h < 0) ? -h : h;
    return (h >= HH) ? (2 * HH - 2 - h) : h;
}

// Gaussian taps for ksize=5, sigma=1.1 (OpenCV default), normalized.
#define C0 0.07076630f    /* w[0] = w[4] */
#define C1 0.24446028f    /* w[1] = w[3] */
#define C2 0.36954642f    /* w[2]        */

struct F8 { float v[8]; };
struct H8 { __half2 h[4]; };   // fp16-compressed hb row (8 values, 16 bytes)

static __device__ __forceinline__ H8 packF8(const F8& f) {
    H8 o;
    #pragma unroll
    for (int j = 0; j < 4; j++)
        o.h[j] = __floats2half2_rn(f.v[2 * j], f.v[2 * j + 1]);
    return o;
}

// Load row h and horizontally blur this thread's 8 floats (flats 8g..8g+7).
// Intra-warp halo via shuffles; warp-edge lanes load their 6-float halo;
// image width edges fold reflect-101 into a register permutation.
static __device__ __forceinline__ F8 hb_row(
    const float* __restrict__ ib, int h, int g, int lane)
{
    const float* __restrict__ rp = ib + (long)hrefl(h) * ROWF + 8 * g;
    float4 Cb = *(const float4*)(rp);       // flats 8g   .. 8g+3
    float4 Db = *(const float4*)(rp + 4);   // flats 8g+4 .. 8g+7

    // e[k] = flat(8g - 6 + k), k = 0..19
    float e0  = __shfl_up_sync(0xffffffffu, Cb.z, 1);
    float e1  = __shfl_up_sync(0xffffffffu, Cb.w, 1);
    float e2  = __shfl_up_sync(0xffffffffu, Db.x, 1);
    float e3  = __shfl_up_sync(0xffffffffu, Db.y, 1);
    float e4  = __shfl_up_sync(0xffffffffu, Db.z, 1);
    float e5  = __shfl_up_sync(0xffffffffu, Db.w, 1);
    float e14 = __shfl_down_sync(0xffffffffu, Cb.x, 1);
    float e15 = __shfl_down_sync(0xffffffffu, Cb.y, 1);
    float e16 = __shfl_down_sync(0xffffffffu, Cb.z, 1);
    float e17 = __shfl_down_sync(0xffffffffu, Cb.w, 1);
    float e18 = __shfl_down_sync(0xffffffffu, Db.x, 1);
    float e19 = __shfl_down_sync(0xffffffffu, Db.y, 1);

    if (lane == 0 && g > 0) {
        float2 a = *(const float2*)(rp - 6);
        float4 b = *(const float4*)(rp - 4);
        e0 = a.x; e1 = a.y; e2 = b.x; e3 = b.y; e4 = b.z; e5 = b.w;
    }
    if (lane == 31 && g < NCOLS - 1) {
        float4 b = *(const float4*)(rp + 8);
        float2 a = *(const float2*)(rp + 12);
        e14 = b.x; e15 = b.y; e16 = b.z; e17 = b.w; e18 = a.x; e19 = a.y;
    }
    if (g == 0) {            // flats -6..-1 -> reflected {6,7,8,3,4,5}
        e0 = Db.z; e1 = Db.w; e2 = e14; e3 = Cb.w; e4 = Db.x; e5 = Db.y;
    }
    if (g == NCOLS - 1) {    // flats 1536..1541 -> {1530,1531,1532,1527,1528,1529}
        e14 = Cb.z; e15 = Cb.w; e16 = Db.x; e17 = e5; e18 = Cb.x; e19 = Cb.y;
    }

    const float e6 = Cb.x, e7 = Cb.y, e8 = Cb.z, e9 = Cb.w;
    const float e10 = Db.x, e11 = Db.y, e12 = Db.z, e13 = Db.w;

    // Horizontal taps at flat offsets {-6,-3,0,+3,+6}.
    F8 o;
    o.v[0] = C0 * (e0 + e12) + C1 * (e3  + e9)  + C2 * e6;
    o.v[1] = C0 * (e1 + e13) + C1 * (e4  + e10) + C2 * e7;
    o.v[2] = C0 * (e2 + e14) + C1 * (e5  + e11) + C2 * e8;
    o.v[3] = C0 * (e3 + e15) + C1 * (e6  + e12) + C2 * e9;
    o.v[4] = C0 * (e4 + e16) + C1 * (e7  + e13) + C2 * e10;
    o.v[5] = C0 * (e5 + e17) + C1 * (e8  + e14) + C2 * e11;
    o.v[6] = C0 * (e6 + e18) + C1 * (e9  + e15) + C2 * e12;
    o.v[7] = C0 * (e7 + e19) + C1 * (e10 + e16) + C2 * e13;
    return o;
}

__global__ void __launch_bounds__(TPB, 4)
gauss5_kernel(const float* __restrict__ x, float* __restrict__ y)
{
    const int t    = threadIdx.x;
    const int lane = t & 31;
    const int h0   = blockIdx.x * BAND;
    const long img = blockIdx.y;

    const float* __restrict__ ib = x + img * (long)(HH * ROWF);
    float*       __restrict__ ob = y + img * (long)(HH * ROWF) + 8 * t;

    // 4-row sliding window of horizontally-blurred values, fp16-compressed.
    H8 w0 = packF8(hb_row(ib, h0 - 2, t, lane));
    H8 w1 = packF8(hb_row(ib, h0 - 1, t, lane));
    H8 w2 = packF8(hb_row(ib, h0,     t, lane));
    H8 w3 = packF8(hb_row(ib, h0 + 1, t, lane));

    // unroll 8: lets ptxas batch up to 8 independent row loads per group.
    #pragma unroll 8
    for (int r = 0; r < BAND; r++) {
        F8 w4 = hb_row(ib, h0 + r + 2, t, lane);

        // Vertical pass: unpack window to fp32, combine in fp32.
        float o[8];
        #pragma unroll
        for (int j = 0; j < 4; j++) {
            float2 f0 = __half22float2(w0.h[j]);
            float2 f1 = __half22float2(w1.h[j]);
            float2 f2 = __half22float2(w2.h[j]);
            float2 f3 = __half22float2(w3.h[j]);
            o[2 * j]     = C0 * (f0.x + w4.v[2 * j])     + C1 * (f1.x + f3.x) + C2 * f2.x;
            o[2 * j + 1] = C0 * (f0.y + w4.v[2 * j + 1]) + C1 * (f1.y + f3.y) + C2 * f2.y;
        }

        float* op = ob + (long)(h0 + r) * ROWF;
        *(float4*)op       = make_float4(o[0], o[1], o[2], o[3]);
        *(float4*)(op + 4) = make_float4(o[4], o[5], o[6], o[7]);

        w0 = w1; w1 = w2; w2 = w3; w3 = packF8(w4);
    }
}

extern "C" void kernel_launch(void* const* d_in, const int* in_sizes, int n_in,
                              void* d_out, int out_size)
{
    const float* x = (const float*)d_in[0];
    float* y = (float*)d_out;
    const int batch = in_sizes[0] / (HH * ROWF);   // 64
    dim3 grid(NBANDS, batch);
    gauss5_kernel<<<grid, TPB>>>(x, y);
}

// round 14
// speedup vs baseline: 1.1614x; 1.0342x over previous
#include <cuda_runtime.h>
#include <cuda_fp16.h>

#define TPB    192        // one thread per 8 floats of a 1536-float row
#define NCOLS  192
#define BAND   16         // output rows per block
#define HH     384
#define ROWF   1536       // W*C floats per row
#define NBANDS (HH / BAND)
#define PFDIST 4          // prefetch distance in rows

static __device__ __forceinline__ int hrefl(int h) {
    // reflect-101 along height; valid for |h| < 2*HH-1 (we use [-2, HH+5])
    h = (h < 0) ? -h : h;
    return (h >= HH) ? (2 * HH - 2 - h) : h;
}

// Gaussian taps for ksize=5, sigma=1.1 (OpenCV default), normalized.
#define C0 0.07076630f    /* w[0] = w[4] */
#define C1 0.24446028f    /* w[1] = w[3] */
#define C2 0.36954642f    /* w[2]        */

struct F8 { float v[8]; };
struct H8 { __half2 h[4]; };   // fp16-compressed hb row (8 values, 16 bytes)

static __device__ __forceinline__ H8 packF8(const F8& f) {
    H8 o;
    #pragma unroll
    for (int j = 0; j < 4; j++)
        o.h[j] = __floats2half2_rn(f.v[2 * j], f.v[2 * j + 1]);
    return o;
}

// Load row h and horizontally blur this thread's 8 floats (flats 8g..8g+7).
// Intra-warp halo via shuffles; warp-edge lanes load their 6-float halo;
// image width edges fold reflect-101 into a register permutation.
static __device__ __forceinline__ F8 hb_row(
    const float* __restrict__ ib, int h, int g, int lane)
{
    const float* __restrict__ rp = ib + (long)hrefl(h) * ROWF + 8 * g;
    float4 Cb = *(const float4*)(rp);       // flats 8g   .. 8g+3
    float4 Db = *(const float4*)(rp + 4);   // flats 8g+4 .. 8g+7

    // e[k] = flat(8g - 6 + k), k = 0..19
    float e0  = __shfl_up_sync(0xffffffffu, Cb.z, 1);
    float e1  = __shfl_up_sync(0xffffffffu, Cb.w, 1);
    float e2  = __shfl_up_sync(0xffffffffu, Db.x, 1);
    float e3  = __shfl_up_sync(0xffffffffu, Db.y, 1);
    float e4  = __shfl_up_sync(0xffffffffu, Db.z, 1);
    float e5  = __shfl_up_sync(0xffffffffu, Db.w, 1);
    float e14 = __shfl_down_sync(0xffffffffu, Cb.x, 1);
    float e15 = __shfl_down_sync(0xffffffffu, Cb.y, 1);
    float e16 = __shfl_down_sync(0xffffffffu, Cb.z, 1);
    float e17 = __shfl_down_sync(0xffffffffu, Cb.w, 1);
    float e18 = __shfl_down_sync(0xffffffffu, Db.x, 1);
    float e19 = __shfl_down_sync(0xffffffffu, Db.y, 1);

    if (lane == 0 && g > 0) {
        float2 a = *(const float2*)(rp - 6);
        float4 b = *(const float4*)(rp - 4);
        e0 = a.x; e1 = a.y; e2 = b.x; e3 = b.y; e4 = b.z; e5 = b.w;
    }
    if (lane == 31 && g < NCOLS - 1) {
        float4 b = *(const float4*)(rp + 8);
        float2 a = *(const float2*)(rp + 12);
        e14 = b.x; e15 = b.y; e16 = b.z; e17 = b.w; e18 = a.x; e19 = a.y;
    }
    if (g == 0) {            // flats -6..-1 -> reflected {6,7,8,3,4,5}
        e0 = Db.z; e1 = Db.w; e2 = e14; e3 = Cb.w; e4 = Db.x; e5 = Db.y;
    }
    if (g == NCOLS - 1) {    // flats 1536..1541 -> {1530,1531,1532,1527,1528,1529}
        e14 = Cb.z; e15 = Cb.w; e16 = Db.x; e17 = e5; e18 = Cb.x; e19 = Cb.y;
    }

    const float e6 = Cb.x, e7 = Cb.y, e8 = Cb.z, e9 = Cb.w;
    const float e10 = Db.x, e11 = Db.y, e12 = Db.z, e13 = Db.w;

    // Horizontal taps at flat offsets {-6,-3,0,+3,+6}.
    F8 o;
    o.v[0] = C0 * (e0 + e12) + C1 * (e3  + e9)  + C2 * e6;
    o.v[1] = C0 * (e1 + e13) + C1 * (e4  + e10) + C2 * e7;
    o.v[2] = C0 * (e2 + e14) + C1 * (e5  + e11) + C2 * e8;
    o.v[3] = C0 * (e3 + e15) + C1 * (e6  + e12) + C2 * e9;
    o.v[4] = C0 * (e4 + e16) + C1 * (e7  + e13) + C2 * e10;
    o.v[5] = C0 * (e5 + e17) + C1 * (e8  + e14) + C2 * e11;
    o.v[6] = C0 * (e6 + e18) + C1 * (e9  + e15) + C2 * e12;
    o.v[7] = C0 * (e7 + e19) + C1 * (e10 + e16) + C2 * e13;
    return o;
}

__global__ void __launch_bounds__(TPB, 4)
gauss5_kernel(const float* __restrict__ x, float* __restrict__ y)
{
    const int t    = threadIdx.x;
    const int lane = t & 31;
    const int h0   = blockIdx.x * BAND;
    const long img = blockIdx.y;

    const float* __restrict__ ib = x + img * (long)(HH * ROWF);
    float*       __restrict__ ob = y + img * (long)(HH * ROWF) + 8 * t;

    // Warp-chunk base for L2 prefetch: lanes 0..7 cover the warp's 1KB row
    // chunk at 128B strides.
    const int pfoff = (t & ~31) * 8 + (lane << 5);

    // Prologue prefetch: rows h0+2 .. h0+2+PFDIST-1.
    if (lane < 8) {
        #pragma unroll
        for (int q = 0; q < PFDIST; q++) {
            const float* pf = ib + (long)hrefl(h0 + 2 + q) * ROWF + pfoff;
            asm volatile("prefetch.global.L2 [%0];" :: "l"(pf));
        }
    }

    // 4-row sliding window of horizontally-blurred values, fp16-compressed.
    H8 w0 = packF8(hb_row(ib, h0 - 2, t, lane));
    H8 w1 = packF8(hb_row(ib, h0 - 1, t, lane));
    H8 w2 = packF8(hb_row(ib, h0,     t, lane));
    H8 w3 = packF8(hb_row(ib, h0 + 1, t, lane));

    // unroll 8: lets ptxas batch independent row loads per group.
    #pragma unroll 8
    for (int r = 0; r < BAND; r++) {
        // Register-free look-ahead: pull row r+2+PFDIST into L2.
        if (lane < 8) {
            const float* pf = ib + (long)hrefl(h0 + r + 2 + PFDIST) * ROWF + pfoff;
            asm volatile("prefetch.global.L2 [%0];" :: "l"(pf));
        }

        F8 w4 = hb_row(ib, h0 + r + 2, t, lane);

        // Vertical pass: unpack window to fp32, combine in fp32.
        float o[8];
        #pragma unroll
        for (int j = 0; j < 4; j++) {
            float2 f0 = __half22float2(w0.h[j]);
            float2 f1 = __half22float2(w1.h[j]);
            float2 f2 = __half22float2(w2.h[j]);
            float2 f3 = __half22float2(w3.h[j]);
            o[2 * j]     = C0 * (f0.x + w4.v[2 * j])     + C1 * (f1.x + f3.x) + C2 * f2.x;
            o[2 * j + 1] = C0 * (f0.y + w4.v[2 * j + 1]) + C1 * (f1.y + f3.y) + C2 * f2.y;
        }

        float* op = ob + (long)(h0 + r) * ROWF;
        *(float4*)op       = make_float4(o[0], o[1], o[2], o[3]);
        *(float4*)(op + 4) = make_float4(o[4], o[5], o[6], o[7]);

        w0 = w1; w1 = w2; w2 = w3; w3 = packF8(w4);
    }
}

extern "C" void kernel_launch(void* const* d_in, const int* in_sizes, int n_in,
                              void* d_out, int out_size)
{
    const float* x = (const float*)d_in[0];
    float* y = (float*)d_out;
    const int batch = in_sizes[0] / (HH * ROWF);   // 64
    dim3 grid(NBANDS, batch);
    gauss5_kernel<<<grid, TPB>>>(x, y);
}